// round 9
// baseline (speedup 1.0000x reference)
#include <cuda_runtime.h>
#include <cuda_bf16.h>
#include <math.h>
#include <stdint.h>

#define NV   262144
#define NE   786432
#define CIMG 256
#define HID  128
#define HW   64
#define NPIX (HW*HW)
#define DIN  (HID+3)
#define BM   64
#define KP   136                 // padded K stride (bf16) -> conflict-free ldmatrix
#define NBLK (NV/BM)             // 4096
#define DEGCAP 32

// Scratch (allowed: __device__ globals, no allocation)
__device__ float g_P[NPIX * HID];                  // 2 MB, L2-resident
__device__ float g_bufA[(size_t)NV * HID];
__device__ float g_bufB[(size_t)NV * HID];
__device__ float g_bufZ[(size_t)NV * HID];
__device__ float g_bufZ2[(size_t)NV * HID];
__device__ __nv_bfloat16 g_Bhi[6 * 16384];         // weights bf16 hi, [n][k] row-major
__device__ __nv_bfloat16 g_Blo[6 * 16384];         // weights bf16 lo
__device__ int g_cnt[NV];
__device__ int g_adj[(size_t)NV * DEGCAP];

// ---------------- helpers ----------------
__device__ __forceinline__ void mma16816(float* c, const uint32_t* a, const uint32_t* b) {
    asm volatile(
        "mma.sync.aligned.m16n8k16.row.col.f32.bf16.bf16.f32 "
        "{%0,%1,%2,%3}, {%4,%5,%6,%7}, {%8,%9}, {%0,%1,%2,%3};"
        : "+f"(c[0]), "+f"(c[1]), "+f"(c[2]), "+f"(c[3])
        : "r"(a[0]), "r"(a[1]), "r"(a[2]), "r"(a[3]), "r"(b[0]), "r"(b[1]));
}
__device__ __forceinline__ void ldmx4(uint32_t* r, uint32_t addr) {
    asm volatile("ldmatrix.sync.aligned.m8n8.x4.shared.b16 {%0,%1,%2,%3}, [%4];"
        : "=r"(r[0]), "=r"(r[1]), "=r"(r[2]), "=r"(r[3]) : "r"(addr));
}
__device__ __forceinline__ uint32_t pack_bf2(__nv_bfloat16 a, __nv_bfloat16 b) {
    return (uint32_t)__bfloat16_as_ushort(a) | ((uint32_t)__bfloat16_as_ushort(b) << 16);
}
__device__ __forceinline__ void split_store(__nv_bfloat16* Ah, __nv_bfloat16* Al,
                                            int off, float4 v) {
    __nv_bfloat16 hx = __float2bfloat16(v.x), hy = __float2bfloat16(v.y);
    __nv_bfloat16 hz = __float2bfloat16(v.z), hw = __float2bfloat16(v.w);
    uint2 hp, lp;
    hp.x = pack_bf2(hx, hy);
    hp.y = pack_bf2(hz, hw);
    lp.x = pack_bf2(__float2bfloat16(v.x - __bfloat162float(hx)),
                    __float2bfloat16(v.y - __bfloat162float(hy)));
    lp.y = pack_bf2(__float2bfloat16(v.z - __bfloat162float(hz)),
                    __float2bfloat16(v.w - __bfloat162float(hw)));
    *(uint2*)&Ah[off] = hp;
    *(uint2*)&Al[off] = lp;
}

// ---------------- kernel 0: weights -> bf16 hi/lo, [n][k] row-major ----------------
__global__ void convw_kernel(const float* __restrict__ w0, const float* __restrict__ w1) {
    int idx = blockIdx.x * 256 + threadIdx.x;
    int m = idx >> 14;
    int e = idx & 16383;
    int n = e & 127;
    int k = e >> 7;
    const float* W = (m < 3) ? (w0 + (size_t)m * DIN * HID) : (w1 + (size_t)(m - 3) * DIN * HID);
    float v = W[(size_t)k * HID + n];
    __nv_bfloat16 hi = __float2bfloat16(v);
    float lo = v - __bfloat162float(hi);
    g_Bhi[(size_t)m * 16384 + n * 128 + k] = hi;
    g_Blo[(size_t)m * 16384 + n * 128 + k] = __float2bfloat16(lo);
}

// ---------------- kernel 1: P[p][j] = sum_c x[c][p] * bw[c][j] ----------------
__global__ void pixel_proj_kernel(const float* __restrict__ x, const float* __restrict__ bw) {
    int j = threadIdx.x;
    int p = blockIdx.x * blockDim.y + threadIdx.y;
    const float* xp = x + p;
    const float* wp = bw + j;
    float acc = 0.f;
    #pragma unroll 8
    for (int c = 0; c < CIMG; c++)
        acc = fmaf(xp[(size_t)c * NPIX], wp[(size_t)c * HID], acc);
    g_P[(size_t)p * HID + j] = acc;
}

// ---------------- adjacency build ----------------
__global__ void zero_cnt_kernel() {
    int v = blockIdx.x * 1024 + threadIdx.x;
    if (v < NV) g_cnt[v] = 0;
}
__global__ void fill_adj_kernel(const int* __restrict__ edges) {
    int e = blockIdx.x * 256 + threadIdx.x;
    if (e >= NE) return;
    int a = edges[2 * e], b = edges[2 * e + 1];
    int sa = atomicAdd(&g_cnt[a], 1);
    if (sa < DEGCAP) g_adj[(size_t)a * DEGCAP + sa] = b;
    int sb = atomicAdd(&g_cnt[b], 1);
    if (sb < DEGCAP) g_adj[(size_t)b * DEGCAP + sb] = a;
}

// ---------------- dual GEMM: stage A once, produce Y and Z ----------------
// mode 0: A = relu(bilinear(g_P, verts) + bbias)
// mode 1: A = relu(Yp[v] + sum_nbr Zp[nbr])     (gather fused into staging)
// OutY = A @ WY[0:128] + verts @ WY[128:131] + biasY   (likewise OutZ)
#define SM_A   0
#define SM_B   (BM * KP * 2 * 2)                  // 34816
#define SM_EPI (SM_B + 128 * KP * 2 * 2)          // 34816 + 69632 = 104448
#define GEMM_SMEM (SM_EPI + 1024 * 4)             // 108544

struct Frag { uint32_t aH0, aH1, aL0, aL1, bH0, bH1, bL0, bL1; };

__device__ __forceinline__ void mainloop(const Frag& F, float acc[2][4][4]) {
    #pragma unroll
    for (int i = 0; i < 2; i++)
        #pragma unroll
        for (int j = 0; j < 4; j++)
            #pragma unroll
            for (int q = 0; q < 4; q++) acc[i][j][q] = 0.f;
    #pragma unroll
    for (int kb = 0; kb < 8; kb++) {
        uint32_t aH[2][4], aL[2][4], bH[2][4], bL[2][4];
        int ko = kb * 32;
        ldmx4(aH[0], F.aH0 + ko); ldmx4(aH[1], F.aH1 + ko);
        ldmx4(aL[0], F.aL0 + ko); ldmx4(aL[1], F.aL1 + ko);
        ldmx4(bH[0], F.bH0 + ko); ldmx4(bH[1], F.bH1 + ko);
        ldmx4(bL[0], F.bL0 + ko); ldmx4(bL[1], F.bL1 + ko);
        #pragma unroll
        for (int i = 0; i < 2; i++)
            #pragma unroll
            for (int j = 0; j < 4; j++) {
                const uint32_t* bh = &bH[j >> 1][(j & 1) * 2];
                const uint32_t* bl = &bL[j >> 1][(j & 1) * 2];
                mma16816(acc[i][j], aH[i], bh);
                mma16816(acc[i][j], aH[i], bl);
                mma16816(acc[i][j], aL[i], bh);
            }
    }
}

__global__ void __launch_bounds__(256, 2)
dual_gemm_kernel(const float* __restrict__ Yp, const float* __restrict__ Zp,
                 const float* __restrict__ verts,
                 const __nv_bfloat16* __restrict__ BhiY, const __nv_bfloat16* __restrict__ BloY,
                 const __nv_bfloat16* __restrict__ BhiZ, const __nv_bfloat16* __restrict__ BloZ,
                 const float* __restrict__ WmY, const float* __restrict__ biasY,
                 const float* __restrict__ WmZ, const float* __restrict__ biasZ,
                 float* __restrict__ OutY, float* __restrict__ OutZ,
                 int mode, const float* __restrict__ bbias) {
    extern __shared__ char smraw[];
    __nv_bfloat16* Ah = (__nv_bfloat16*)(smraw + SM_A);        // BM x KP
    __nv_bfloat16* Al = Ah + BM * KP;
    __nv_bfloat16* Bh = (__nv_bfloat16*)(smraw + SM_B);        // 128 x KP
    __nv_bfloat16* Bl = Bh + 128 * KP;
    float* epi = (float*)(smraw + SM_EPI);                     // [0:512) Y-set, [512:1024) Z-set

    const int tid = threadIdx.x, lane = tid & 31, wid = tid >> 5;

    // stage B for Y-set
    {
        const uint4* gh = (const uint4*)BhiY;
        const uint4* gl = (const uint4*)BloY;
        #pragma unroll
        for (int i = tid; i < 2048; i += 256) {
            int n = i >> 4, kc = (i & 15) * 8;
            *(uint4*)&Bh[n * KP + kc] = gh[i];
            *(uint4*)&Bl[n * KP + kc] = gl[i];
        }
    }
    if (tid < 128) {
        epi[tid]       = WmY[(size_t)(HID + 0) * HID + tid];
        epi[128 + tid] = WmY[(size_t)(HID + 1) * HID + tid];
        epi[256 + tid] = WmY[(size_t)(HID + 2) * HID + tid];
        epi[384 + tid] = biasY[tid];
        epi[512 + tid] = WmZ[(size_t)(HID + 0) * HID + tid];
        epi[640 + tid] = WmZ[(size_t)(HID + 1) * HID + tid];
        epi[768 + tid] = WmZ[(size_t)(HID + 2) * HID + tid];
        epi[896 + tid] = biasZ[tid];
    }

    // stage A
    if (mode == 0) {
        // fused bilinear sampling from L2-resident g_P
        #pragma unroll
        for (int i = tid; i < BM * HID / 4; i += 256) {
            int r = i >> 5, c = (i & 31) * 4;
            int vtx = blockIdx.x * BM + r;
            float vx = verts[3 * vtx], vy = verts[3 * vtx + 1];
            float px = (vx + 1.f) * 0.5f * (HW - 1);
            float py = (vy + 1.f) * 0.5f * (HW - 1);
            float fx = floorf(px), fy = floorf(py);
            float wx = px - fx,    wy = py - fy;
            int x0 = (int)fx; x0 = min(max(x0, 0), HW - 1); int x1 = min(x0 + 1, HW - 1);
            int y0 = (int)fy; y0 = min(max(y0, 0), HW - 1); int y1 = min(y0 + 1, HW - 1);
            const float* P00 = g_P + (size_t)(y0 * HW + x0) * HID;
            const float* P01 = g_P + (size_t)(y0 * HW + x1) * HID;
            const float* P10 = g_P + (size_t)(y1 * HW + x0) * HID;
            const float* P11 = g_P + (size_t)(y1 * HW + x1) * HID;
            float4 a = *(const float4*)(P00 + c);
            float4 b = *(const float4*)(P01 + c);
            float4 cc = *(const float4*)(P10 + c);
            float4 d = *(const float4*)(P11 + c);
            float4 b4 = *(const float4*)(bbias + c);
            float4 v;
            v.x = (a.x * (1.f - wx) + b.x * wx) * (1.f - wy) + (cc.x * (1.f - wx) + d.x * wx) * wy + b4.x;
            v.y = (a.y * (1.f - wx) + b.y * wx) * (1.f - wy) + (cc.y * (1.f - wx) + d.y * wx) * wy + b4.y;
            v.z = (a.z * (1.f - wx) + b.z * wx) * (1.f - wy) + (cc.z * (1.f - wx) + d.z * wx) * wy + b4.z;
            v.w = (a.w * (1.f - wx) + b.w * wx) * (1.f - wy) + (cc.w * (1.f - wx) + d.w * wx) * wy + b4.w;
            v.x = fmaxf(v.x, 0.f); v.y = fmaxf(v.y, 0.f);
            v.z = fmaxf(v.z, 0.f); v.w = fmaxf(v.w, 0.f);
            split_store(Ah, Al, r * KP + c, v);
        }
    } else {
        // fused gather: warp per row, 8 rows per warp
        #pragma unroll 1
        for (int s = 0; s < 8; s++) {
            int r = wid * 8 + s;
            int v = blockIdx.x * BM + r;
            int cnt = min(g_cnt[v], DEGCAP);
            int u = (lane < cnt) ? g_adj[(size_t)v * DEGCAP + lane] : 0;
            float4 acc4 = *(const float4*)(Yp + (size_t)v * HID + lane * 4);
            int i = 0;
            for (; i + 2 <= cnt; i += 2) {
                int u0 = __shfl_sync(0xffffffffu, u, i);
                int u1 = __shfl_sync(0xffffffffu, u, i + 1);
                float4 z0 = *(const float4*)(Zp + (size_t)u0 * HID + lane * 4);
                float4 z1 = *(const float4*)(Zp + (size_t)u1 * HID + lane * 4);
                acc4.x += z0.x + z1.x; acc4.y += z0.y + z1.y;
                acc4.z += z0.z + z1.z; acc4.w += z0.w + z1.w;
            }
            if (i < cnt) {
                int u0 = __shfl_sync(0xffffffffu, u, i);
                float4 z0 = *(const float4*)(Zp + (size_t)u0 * HID + lane * 4);
                acc4.x += z0.x; acc4.y += z0.y; acc4.z += z0.z; acc4.w += z0.w;
            }
            acc4.x = fmaxf(acc4.x, 0.f); acc4.y = fmaxf(acc4.y, 0.f);
            acc4.z = fmaxf(acc4.z, 0.f); acc4.w = fmaxf(acc4.w, 0.f);
            split_store(Ah, Al, r * KP + lane * 4, acc4);
        }
    }
    __syncthreads();

    const int m0 = (wid & 1) * 32;
    const int n0 = (wid >> 1) * 32;
    const int g = lane >> 2, tig = lane & 3;

    // ldmatrix base addresses (byte, shared space)
    Frag F;
    {
        uint32_t sAh = (uint32_t)__cvta_generic_to_shared(Ah);
        uint32_t sAl = (uint32_t)__cvta_generic_to_shared(Al);
        uint32_t sBh = (uint32_t)__cvta_generic_to_shared(Bh);
        uint32_t sBl = (uint32_t)__cvta_generic_to_shared(Bl);
        int arow = (lane & 15), akoff = (lane >> 4) * 8;
        F.aH0 = sAh + ((m0 + arow) * KP + akoff) * 2;
        F.aH1 = sAh + ((m0 + 16 + arow) * KP + akoff) * 2;
        F.aL0 = sAl + ((m0 + arow) * KP + akoff) * 2;
        F.aL1 = sAl + ((m0 + 16 + arow) * KP + akoff) * 2;
        int brow = (lane & 7) + ((lane >> 4) & 1) * 8, bkoff = ((lane >> 3) & 1) * 8;
        F.bH0 = sBh + ((n0 + brow) * KP + bkoff) * 2;
        F.bH1 = sBh + ((n0 + 16 + brow) * KP + bkoff) * 2;
        F.bL0 = sBl + ((n0 + brow) * KP + bkoff) * 2;
        F.bL1 = sBl + ((n0 + 16 + brow) * KP + bkoff) * 2;
    }

    float acc[2][4][4];
    mainloop(F, acc);
    __syncthreads();   // done reading B (Y-set)

    // reload B with Z-set (overlaps epilogue Y)
    {
        const uint4* gh = (const uint4*)BhiZ;
        const uint4* gl = (const uint4*)BloZ;
        #pragma unroll
        for (int i = tid; i < 2048; i += 256) {
            int n = i >> 4, kc = (i & 15) * 8;
            *(uint4*)&Bh[n * KP + kc] = gh[i];
            *(uint4*)&Bl[n * KP + kc] = gl[i];
        }
    }
    // epilogue Y
    #pragma unroll
    for (int i = 0; i < 2; i++) {
        int r0 = blockIdx.x * BM + m0 + i * 16 + g;
        int r1 = r0 + 8;
        float vx0 = verts[3 * r0], vy0 = verts[3 * r0 + 1], vz0 = verts[3 * r0 + 2];
        float vx1 = verts[3 * r1], vy1 = verts[3 * r1 + 1], vz1 = verts[3 * r1 + 2];
        #pragma unroll
        for (int j = 0; j < 4; j++) {
            int c = n0 + j * 8 + 2 * tig;
            float w0a = epi[c],       w0b = epi[c + 1];
            float w1a = epi[128 + c], w1b = epi[128 + c + 1];
            float w2a = epi[256 + c], w2b = epi[256 + c + 1];
            float ba  = epi[384 + c], bb2 = epi[384 + c + 1];
            float2 o01, o23;
            o01.x = acc[i][j][0] + vx0 * w0a + vy0 * w1a + vz0 * w2a + ba;
            o01.y = acc[i][j][1] + vx0 * w0b + vy0 * w1b + vz0 * w2b + bb2;
            o23.x = acc[i][j][2] + vx1 * w0a + vy1 * w1a + vz1 * w2a + ba;
            o23.y = acc[i][j][3] + vx1 * w0b + vy1 * w1b + vz1 * w2b + bb2;
            *(float2*)(OutY + (size_t)r0 * HID + c) = o01;
            *(float2*)(OutY + (size_t)r1 * HID + c) = o23;
        }
    }
    __syncthreads();   // B (Z-set) staged

    mainloop(F, acc);

    // epilogue Z
    #pragma unroll
    for (int i = 0; i < 2; i++) {
        int r0 = blockIdx.x * BM + m0 + i * 16 + g;
        int r1 = r0 + 8;
        float vx0 = verts[3 * r0], vy0 = verts[3 * r0 + 1], vz0 = verts[3 * r0 + 2];
        float vx1 = verts[3 * r1], vy1 = verts[3 * r1 + 1], vz1 = verts[3 * r1 + 2];
        #pragma unroll
        for (int j = 0; j < 4; j++) {
            int c = n0 + j * 8 + 2 * tig;
            float w0a = epi[512 + c],       w0b = epi[512 + c + 1];
            float w1a = epi[640 + c], w1b = epi[640 + c + 1];
            float w2a = epi[768 + c], w2b = epi[768 + c + 1];
            float ba  = epi[896 + c], bb2 = epi[896 + c + 1];
            float2 o01, o23;
            o01.x = acc[i][j][0] + vx0 * w0a + vy0 * w1a + vz0 * w2a + ba;
            o01.y = acc[i][j][1] + vx0 * w0b + vy0 * w1b + vz0 * w2b + bb2;
            o23.x = acc[i][j][2] + vx1 * w0a + vy1 * w1a + vz1 * w2a + ba;
            o23.y = acc[i][j][3] + vx1 * w0b + vy1 * w1b + vz1 * w2b + bb2;
            *(float2*)(OutZ + (size_t)r0 * HID + c) = o01;
            *(float2*)(OutZ + (size_t)r1 * HID + c) = o23;
        }
    }
}

// ---------------- gather + final head fused ----------------
__global__ void gather_final_kernel(const float* __restrict__ Z, const float* __restrict__ Ybuf,
                                    const float* __restrict__ verts,
                                    const float* __restrict__ ow, const float* __restrict__ ob,
                                    float* __restrict__ out) {
    __shared__ float sw[DIN * 3];
    for (int i = threadIdx.x; i < DIN * 3; i += blockDim.x) sw[i] = ow[i];
    __syncthreads();

    int v    = (blockIdx.x * blockDim.x + threadIdx.x) >> 5;
    int lane = threadIdx.x & 31;
    if (v >= NV) return;
    int cnt = min(g_cnt[v], DEGCAP);
    int u = (lane < cnt) ? g_adj[(size_t)v * DEGCAP + lane] : 0;
    float4 acc = *(const float4*)(Ybuf + (size_t)v * HID + lane * 4);
    int i = 0;
    for (; i + 2 <= cnt; i += 2) {
        int u0 = __shfl_sync(0xffffffffu, u, i);
        int u1 = __shfl_sync(0xffffffffu, u, i + 1);
        float4 z0 = *(const float4*)(Z + (size_t)u0 * HID + lane * 4);
        float4 z1 = *(const float4*)(Z + (size_t)u1 * HID + lane * 4);
        acc.x += z0.x + z1.x; acc.y += z0.y + z1.y;
        acc.z += z0.z + z1.z; acc.w += z0.w + z1.w;
    }
    if (i < cnt) {
        int u0 = __shfl_sync(0xffffffffu, u, i);
        float4 z0 = *(const float4*)(Z + (size_t)u0 * HID + lane * 4);
        acc.x += z0.x; acc.y += z0.y; acc.z += z0.z; acc.w += z0.w;
    }

    float4 f;
    f.x = fmaxf(acc.x, 0.f); f.y = fmaxf(acc.y, 0.f);
    f.z = fmaxf(acc.z, 0.f); f.w = fmaxf(acc.w, 0.f);
    int j = lane * 4;
    *(float4*)(out + (size_t)3 * NV + (size_t)v * HID + j) = f;

    float a0 = f.x * sw[(j + 0) * 3 + 0] + f.y * sw[(j + 1) * 3 + 0] + f.z * sw[(j + 2) * 3 + 0] + f.w * sw[(j + 3) * 3 + 0];
    float a1 = f.x * sw[(j + 0) * 3 + 1] + f.y * sw[(j + 1) * 3 + 1] + f.z * sw[(j + 2) * 3 + 1] + f.w * sw[(j + 3) * 3 + 1];
    float a2 = f.x * sw[(j + 0) * 3 + 2] + f.y * sw[(j + 1) * 3 + 2] + f.z * sw[(j + 2) * 3 + 2] + f.w * sw[(j + 3) * 3 + 2];
    #pragma unroll
    for (int off = 16; off > 0; off >>= 1) {
        a0 += __shfl_down_sync(0xffffffffu, a0, off);
        a1 += __shfl_down_sync(0xffffffffu, a1, off);
        a2 += __shfl_down_sync(0xffffffffu, a2, off);
    }
    if (lane == 0) {
        float vx = verts[3 * v], vy = verts[3 * v + 1], vz = verts[3 * v + 2];
        a0 += vx * sw[(HID + 0) * 3 + 0] + vy * sw[(HID + 1) * 3 + 0] + vz * sw[(HID + 2) * 3 + 0] + ob[0];
        a1 += vx * sw[(HID + 0) * 3 + 1] + vy * sw[(HID + 1) * 3 + 1] + vz * sw[(HID + 2) * 3 + 1] + ob[1];
        a2 += vx * sw[(HID + 0) * 3 + 2] + vy * sw[(HID + 1) * 3 + 2] + vz * sw[(HID + 2) * 3 + 2] + ob[2];
        out[3 * v + 0] = vx + tanhf(a0);
        out[3 * v + 1] = vy + tanhf(a1);
        out[3 * v + 2] = vz + tanhf(a2);
    }
}

// ---------------- launch ----------------
extern "C" void kernel_launch(void* const* d_in, const int* in_sizes, int n_in,
                              void* d_out, int out_size) {
    const float* x     = (const float*)d_in[0];
    const float* verts = (const float*)d_in[1];
    const int*   edges = (const int*)  d_in[2];
    const float* bw    = (const float*)d_in[3];
    const float* bb    = (const float*)d_in[4];
    const float* w0    = (const float*)d_in[5];
    const float* b0    = (const float*)d_in[6];
    const float* w1    = (const float*)d_in[7];
    const float* b1    = (const float*)d_in[8];
    const float* ow    = (const float*)d_in[9];
    const float* ob    = (const float*)d_in[10];
    float* out = (float*)d_out;

    float *bufA, *bufB, *bufZ, *bufZ2;
    __nv_bfloat16 *Bhi, *Blo;
    cudaGetSymbolAddress((void**)&bufA, g_bufA);
    cudaGetSymbolAddress((void**)&bufB, g_bufB);
    cudaGetSymbolAddress((void**)&bufZ, g_bufZ);
    cudaGetSymbolAddress((void**)&bufZ2, g_bufZ2);
    cudaGetSymbolAddress((void**)&Bhi, g_Bhi);
    cudaGetSymbolAddress((void**)&Blo, g_Blo);

    cudaFuncSetAttribute(dual_gemm_kernel, cudaFuncAttributeMaxDynamicSharedMemorySize, GEMM_SMEM);

    convw_kernel<<<6 * 16384 / 256, 256>>>(w0, w1);
    pixel_proj_kernel<<<NPIX / 2, dim3(HID, 2)>>>(x, bw);
    zero_cnt_kernel<<<NV / 1024, 1024>>>();
    fill_adj_kernel<<<NE / 256, 256>>>(edges);

    // layer 1 (A from fused bilinear sampling): Y1 -> bufA, Z1 -> bufZ
    dual_gemm_kernel<<<NBLK, 256, GEMM_SMEM>>>(
        nullptr, nullptr, verts,
        Bhi + 0 * 16384, Blo + 0 * 16384, Bhi + 3 * 16384, Blo + 3 * 16384,
        w0, b0, w1, b1,
        bufA, bufZ, 0, bb);

    // layer 2 (A = relu(Y1 + gather(Z1))): Y2 -> bufB, Z2 -> bufZ2
    dual_gemm_kernel<<<NBLK, 256, GEMM_SMEM>>>(
        bufA, bufZ, verts,
        Bhi + 1 * 16384, Blo + 1 * 16384, Bhi + 4 * 16384, Blo + 4 * 16384,
        w0 + (size_t)1 * DIN * HID, b0 + HID, w1 + (size_t)1 * DIN * HID, b1 + HID,
        bufB, bufZ2, 1, bb);

    // layer 3: Y3 -> bufA, Z3 -> bufZ
    dual_gemm_kernel<<<NBLK, 256, GEMM_SMEM>>>(
        bufB, bufZ2, verts,
        Bhi + 2 * 16384, Blo + 2 * 16384, Bhi + 5 * 16384, Blo + 5 * 16384,
        w0 + (size_t)2 * DIN * HID, b0 + 2 * HID, w1 + (size_t)2 * DIN * HID, b1 + 2 * HID,
        bufA, bufZ, 1, bb);

    // final: gather(Z3) + head
    gather_final_kernel<<<NV / 8, 256>>>(bufZ, bufA, verts, ow, ob, out);
}

// round 11
// speedup vs baseline: 1.1291x; 1.1291x over previous
#include <cuda_runtime.h>
#include <cuda_bf16.h>
#include <math.h>
#include <stdint.h>

#define NV   262144
#define NE   786432
#define CIMG 256
#define HID  128
#define HW   64
#define NPIX (HW*HW)
#define DIN  (HID+3)
#define BM   64
#define KP   136                 // padded K stride (bf16) -> conflict-free ldmatrix
#define NBLK (NV/BM)             // 4096
#define DEGCAP 32

// Scratch (allowed: __device__ globals, no allocation)
__device__ float g_P[NPIX * HID];                  // 2 MB, L2-resident
__device__ float g_bufA[(size_t)NV * HID];
__device__ float g_bufB[(size_t)NV * HID];
__device__ float g_bufZ[(size_t)NV * HID];
__device__ __nv_bfloat16 g_Bhi[6 * 16384];         // weights bf16 hi, [n][k] row-major
__device__ __nv_bfloat16 g_Blo[6 * 16384];         // weights bf16 lo
__device__ int g_cnt[NV];
__device__ int g_adj[(size_t)NV * DEGCAP];

// ---------------- helpers ----------------
__device__ __forceinline__ void mma16816(float* c, const uint32_t* a, const uint32_t* b) {
    asm volatile(
        "mma.sync.aligned.m16n8k16.row.col.f32.bf16.bf16.f32 "
        "{%0,%1,%2,%3}, {%4,%5,%6,%7}, {%8,%9}, {%0,%1,%2,%3};"
        : "+f"(c[0]), "+f"(c[1]), "+f"(c[2]), "+f"(c[3])
        : "r"(a[0]), "r"(a[1]), "r"(a[2]), "r"(a[3]), "r"(b[0]), "r"(b[1]));
}
__device__ __forceinline__ void ldmx4(uint32_t* r, uint32_t addr) {
    asm volatile("ldmatrix.sync.aligned.m8n8.x4.shared.b16 {%0,%1,%2,%3}, [%4];"
        : "=r"(r[0]), "=r"(r[1]), "=r"(r[2]), "=r"(r[3]) : "r"(addr));
}
__device__ __forceinline__ uint32_t pack_bf2(__nv_bfloat16 a, __nv_bfloat16 b) {
    return (uint32_t)__bfloat16_as_ushort(a) | ((uint32_t)__bfloat16_as_ushort(b) << 16);
}
__device__ __forceinline__ void split_store(__nv_bfloat16* Ah, __nv_bfloat16* Al,
                                            int off, float4 v) {
    __nv_bfloat16 hx = __float2bfloat16(v.x), hy = __float2bfloat16(v.y);
    __nv_bfloat16 hz = __float2bfloat16(v.z), hw = __float2bfloat16(v.w);
    uint2 hp, lp;
    hp.x = pack_bf2(hx, hy);
    hp.y = pack_bf2(hz, hw);
    lp.x = pack_bf2(__float2bfloat16(v.x - __bfloat162float(hx)),
                    __float2bfloat16(v.y - __bfloat162float(hy)));
    lp.y = pack_bf2(__float2bfloat16(v.z - __bfloat162float(hz)),
                    __float2bfloat16(v.w - __bfloat162float(hw)));
    *(uint2*)&Ah[off] = hp;
    *(uint2*)&Al[off] = lp;
}

// ---------------- kernel 0: weights -> bf16 hi/lo, [n][k] row-major ----------------
__global__ void convw_kernel(const float* __restrict__ w0, const float* __restrict__ w1) {
    int idx = blockIdx.x * 256 + threadIdx.x;
    int m = idx >> 14;
    int e = idx & 16383;
    int n = e & 127;
    int k = e >> 7;
    const float* W = (m < 3) ? (w0 + (size_t)m * DIN * HID) : (w1 + (size_t)(m - 3) * DIN * HID);
    float v = W[(size_t)k * HID + n];
    __nv_bfloat16 hi = __float2bfloat16(v);
    float lo = v - __bfloat162float(hi);
    g_Bhi[(size_t)m * 16384 + n * 128 + k] = hi;
    g_Blo[(size_t)m * 16384 + n * 128 + k] = __float2bfloat16(lo);
}

// ---------------- kernel 1: P[p][j] = sum_c x[c][p] * bw[c][j] ----------------
__global__ void pixel_proj_kernel(const float* __restrict__ x, const float* __restrict__ bw) {
    int j = threadIdx.x;
    int p = blockIdx.x * blockDim.y + threadIdx.y;
    const float* xp = x + p;
    const float* wp = bw + j;
    float acc = 0.f;
    #pragma unroll 8
    for (int c = 0; c < CIMG; c++)
        acc = fmaf(xp[(size_t)c * NPIX], wp[(size_t)c * HID], acc);
    g_P[(size_t)p * HID + j] = acc;
}

// ---------------- adjacency build ----------------
__global__ void zero_cnt_kernel() {
    int v = blockIdx.x * 1024 + threadIdx.x;
    if (v < NV) g_cnt[v] = 0;
}
__global__ void fill_adj_kernel(const int* __restrict__ edges) {
    int e = blockIdx.x * 256 + threadIdx.x;
    if (e >= NE) return;
    int a = edges[2 * e], b = edges[2 * e + 1];
    int sa = atomicAdd(&g_cnt[a], 1);
    if (sa < DEGCAP) g_adj[(size_t)a * DEGCAP + sa] = b;
    int sb = atomicAdd(&g_cnt[b], 1);
    if (sb < DEGCAP) g_adj[(size_t)b * DEGCAP + sb] = a;
}

// ---------------- gather: Y[v] += sum_nbr Z[nbr]  (in-place on Y) ----------------
__global__ void gather_kernel(const float* __restrict__ Z, float* __restrict__ Y) {
    int v    = (blockIdx.x * blockDim.x + threadIdx.x) >> 5;
    int lane = threadIdx.x & 31;
    if (v >= NV) return;
    int cnt = min(g_cnt[v], DEGCAP);
    int u = (lane < cnt) ? g_adj[(size_t)v * DEGCAP + lane] : 0;
    float4 acc = *(const float4*)(Y + (size_t)v * HID + lane * 4);
    int i = 0;
    for (; i + 2 <= cnt; i += 2) {
        int u0 = __shfl_sync(0xffffffffu, u, i);
        int u1 = __shfl_sync(0xffffffffu, u, i + 1);
        float4 z0 = *(const float4*)(Z + (size_t)u0 * HID + lane * 4);
        float4 z1 = *(const float4*)(Z + (size_t)u1 * HID + lane * 4);
        acc.x += z0.x + z1.x; acc.y += z0.y + z1.y;
        acc.z += z0.z + z1.z; acc.w += z0.w + z1.w;
    }
    if (i < cnt) {
        int u0 = __shfl_sync(0xffffffffu, u, i);
        float4 z0 = *(const float4*)(Z + (size_t)u0 * HID + lane * 4);
        acc.x += z0.x; acc.y += z0.y; acc.z += z0.z; acc.w += z0.w;
    }
    *(float4*)(Y + (size_t)v * HID + lane * 4) = acc;
}

// ---------------- gather + final head fused (layer 3) ----------------
__global__ void gather_final_kernel(const float* __restrict__ Z, const float* __restrict__ Ybuf,
                                    const float* __restrict__ verts,
                                    const float* __restrict__ ow, const float* __restrict__ ob,
                                    float* __restrict__ out) {
    __shared__ float sw[DIN * 3];
    for (int i = threadIdx.x; i < DIN * 3; i += blockDim.x) sw[i] = ow[i];
    __syncthreads();

    int v    = (blockIdx.x * blockDim.x + threadIdx.x) >> 5;
    int lane = threadIdx.x & 31;
    if (v >= NV) return;
    int cnt = min(g_cnt[v], DEGCAP);
    int u = (lane < cnt) ? g_adj[(size_t)v * DEGCAP + lane] : 0;
    float4 acc = *(const float4*)(Ybuf + (size_t)v * HID + lane * 4);
    int i = 0;
    for (; i + 2 <= cnt; i += 2) {
        int u0 = __shfl_sync(0xffffffffu, u, i);
        int u1 = __shfl_sync(0xffffffffu, u, i + 1);
        float4 z0 = *(const float4*)(Z + (size_t)u0 * HID + lane * 4);
        float4 z1 = *(const float4*)(Z + (size_t)u1 * HID + lane * 4);
        acc.x += z0.x + z1.x; acc.y += z0.y + z1.y;
        acc.z += z0.z + z1.z; acc.w += z0.w + z1.w;
    }
    if (i < cnt) {
        int u0 = __shfl_sync(0xffffffffu, u, i);
        float4 z0 = *(const float4*)(Z + (size_t)u0 * HID + lane * 4);
        acc.x += z0.x; acc.y += z0.y; acc.z += z0.z; acc.w += z0.w;
    }

    float4 f;
    f.x = fmaxf(acc.x, 0.f); f.y = fmaxf(acc.y, 0.f);
    f.z = fmaxf(acc.z, 0.f); f.w = fmaxf(acc.w, 0.f);
    int j = lane * 4;
    *(float4*)(out + (size_t)3 * NV + (size_t)v * HID + j) = f;

    float a0 = f.x * sw[(j + 0) * 3 + 0] + f.y * sw[(j + 1) * 3 + 0] + f.z * sw[(j + 2) * 3 + 0] + f.w * sw[(j + 3) * 3 + 0];
    float a1 = f.x * sw[(j + 0) * 3 + 1] + f.y * sw[(j + 1) * 3 + 1] + f.z * sw[(j + 2) * 3 + 1] + f.w * sw[(j + 3) * 3 + 1];
    float a2 = f.x * sw[(j + 0) * 3 + 2] + f.y * sw[(j + 1) * 3 + 2] + f.z * sw[(j + 2) * 3 + 2] + f.w * sw[(j + 3) * 3 + 2];
    #pragma unroll
    for (int off = 16; off > 0; off >>= 1) {
        a0 += __shfl_down_sync(0xffffffffu, a0, off);
        a1 += __shfl_down_sync(0xffffffffu, a1, off);
        a2 += __shfl_down_sync(0xffffffffu, a2, off);
    }
    if (lane == 0) {
        float vx = verts[3 * v], vy = verts[3 * v + 1], vz = verts[3 * v + 2];
        a0 += vx * sw[(HID + 0) * 3 + 0] + vy * sw[(HID + 1) * 3 + 0] + vz * sw[(HID + 2) * 3 + 0] + ob[0];
        a1 += vx * sw[(HID + 0) * 3 + 1] + vy * sw[(HID + 1) * 3 + 1] + vz * sw[(HID + 2) * 3 + 1] + ob[1];
        a2 += vx * sw[(HID + 0) * 3 + 2] + vy * sw[(HID + 1) * 3 + 2] + vz * sw[(HID + 2) * 3 + 2] + ob[2];
        out[3 * v + 0] = vx + tanhf(a0);
        out[3 * v + 1] = vy + tanhf(a1);
        out[3 * v + 2] = vz + tanhf(a2);
    }
}

// ---------------- kernel 3: HMMA GEMM (bf16 hi/lo split, 3 terms, ldmatrix) ----------------
// sample_mode=0: A-tile = relu(A[V,128])
// sample_mode=1: A-tile = relu(bilinear(g_P, verts) + bbias)   (layer-1 fusion)
// Out = Atile @ W[0:128] + verts @ W[128:131] + bias
#define GEMM_SMEM ((BM*KP*2 + 128*KP*2) * 2 + 512 * 4)   // 106496 B

struct Frag { uint32_t aH0, aH1, aL0, aL1, bH0, bH1, bL0, bL1; };

__device__ __forceinline__ void mainloop(const Frag& F, float acc[2][4][4]) {
    #pragma unroll
    for (int i = 0; i < 2; i++)
        #pragma unroll
        for (int j = 0; j < 4; j++)
            #pragma unroll
            for (int q = 0; q < 4; q++) acc[i][j][q] = 0.f;
    #pragma unroll
    for (int kb = 0; kb < 8; kb++) {
        uint32_t aH[2][4], aL[2][4], bH[2][4], bL[2][4];
        int ko = kb * 32;
        ldmx4(aH[0], F.aH0 + ko); ldmx4(aH[1], F.aH1 + ko);
        ldmx4(aL[0], F.aL0 + ko); ldmx4(aL[1], F.aL1 + ko);
        ldmx4(bH[0], F.bH0 + ko); ldmx4(bH[1], F.bH1 + ko);
        ldmx4(bL[0], F.bL0 + ko); ldmx4(bL[1], F.bL1 + ko);
        #pragma unroll
        for (int i = 0; i < 2; i++)
            #pragma unroll
            for (int j = 0; j < 4; j++) {
                const uint32_t* bh = &bH[j >> 1][(j & 1) * 2];
                const uint32_t* bl = &bL[j >> 1][(j & 1) * 2];
                mma16816(acc[i][j], aH[i], bh);
                mma16816(acc[i][j], aH[i], bl);
                mma16816(acc[i][j], aL[i], bh);
            }
    }
}

__global__ void __launch_bounds__(256, 2)
gemm_mma_kernel(const float* __restrict__ A, const float* __restrict__ verts,
                const __nv_bfloat16* __restrict__ Bhi, const __nv_bfloat16* __restrict__ Blo,
                const float* __restrict__ Wm, const float* __restrict__ bias,
                float* __restrict__ Out, int sample_mode, const float* __restrict__ bbias) {
    extern __shared__ char smraw[];
    __nv_bfloat16* Ah = (__nv_bfloat16*)smraw;         // BM x KP
    __nv_bfloat16* Al = Ah + BM * KP;
    __nv_bfloat16* Bh = Al + BM * KP;                  // 128 x KP
    __nv_bfloat16* Bl = Bh + 128 * KP;
    float* epi = (float*)(Bl + 128 * KP);              // w128,w129,w130,bias rows

    const int tid = threadIdx.x, lane = tid & 31, wid = tid >> 5;

    // stage B hi/lo (uint4 = 8 bf16)
    {
        const uint4* gh = (const uint4*)Bhi;
        const uint4* gl = (const uint4*)Blo;
        #pragma unroll
        for (int i = tid; i < 2048; i += 256) {
            int n = i >> 4, kc = (i & 15) * 8;
            *(uint4*)&Bh[n * KP + kc] = gh[i];
            *(uint4*)&Bl[n * KP + kc] = gl[i];
        }
    }
    if (tid < 128) {
        epi[tid]       = Wm[(size_t)(HID + 0) * HID + tid];
        epi[128 + tid] = Wm[(size_t)(HID + 1) * HID + tid];
        epi[256 + tid] = Wm[(size_t)(HID + 2) * HID + tid];
        epi[384 + tid] = bias[tid];
    }
    // stage A tile: relu + hi/lo split
    if (!sample_mode) {
        const float* Asrc = A + (size_t)blockIdx.x * BM * HID;
        #pragma unroll
        for (int i = tid; i < BM * HID / 4; i += 256) {   // 2048 float4
            int r = i >> 5, c = (i & 31) * 4;
            float4 v = *(const float4*)(Asrc + (size_t)r * HID + c);
            v.x = fmaxf(v.x, 0.f); v.y = fmaxf(v.y, 0.f);
            v.z = fmaxf(v.z, 0.f); v.w = fmaxf(v.w, 0.f);
            split_store(Ah, Al, r * KP + c, v);
        }
    } else {
        // fused bilinear sampling from L2-resident g_P
        #pragma unroll
        for (int i = tid; i < BM * HID / 4; i += 256) {
            int r = i >> 5, c = (i & 31) * 4;
            int vtx = blockIdx.x * BM + r;
            float vx = verts[3 * vtx], vy = verts[3 * vtx + 1];
            float px = (vx + 1.f) * 0.5f * (HW - 1);
            float py = (vy + 1.f) * 0.5f * (HW - 1);
            float fx = floorf(px), fy = floorf(py);
            float wx = px - fx,    wy = py - fy;
            int x0 = (int)fx; x0 = min(max(x0, 0), HW - 1); int x1 = min(x0 + 1, HW - 1);
            int y0 = (int)fy; y0 = min(max(y0, 0), HW - 1); int y1 = min(y0 + 1, HW - 1);
            const float* P00 = g_P + (size_t)(y0 * HW + x0) * HID;
            const float* P01 = g_P + (size_t)(y0 * HW + x1) * HID;
            const float* P10 = g_P + (size_t)(y1 * HW + x0) * HID;
            const float* P11 = g_P + (size_t)(y1 * HW + x1) * HID;
            float4 a = *(const float4*)(P00 + c);
            float4 b = *(const float4*)(P01 + c);
            float4 cc = *(const float4*)(P10 + c);
            float4 d = *(const float4*)(P11 + c);
            float4 b4 = *(const float4*)(bbias + c);
            float4 v;
            v.x = (a.x * (1.f - wx) + b.x * wx) * (1.f - wy) + (cc.x * (1.f - wx) + d.x * wx) * wy + b4.x;
            v.y = (a.y * (1.f - wx) + b.y * wx) * (1.f - wy) + (cc.y * (1.f - wx) + d.y * wx) * wy + b4.y;
            v.z = (a.z * (1.f - wx) + b.z * wx) * (1.f - wy) + (cc.z * (1.f - wx) + d.z * wx) * wy + b4.z;
            v.w = (a.w * (1.f - wx) + b.w * wx) * (1.f - wy) + (cc.w * (1.f - wx) + d.w * wx) * wy + b4.w;
            v.x = fmaxf(v.x, 0.f); v.y = fmaxf(v.y, 0.f);
            v.z = fmaxf(v.z, 0.f); v.w = fmaxf(v.w, 0.f);
            split_store(Ah, Al, r * KP + c, v);
        }
    }
    __syncthreads();

    const int m0 = (wid & 1) * 32;     // warp m-offset within tile
    const int n0 = (wid >> 1) * 32;    // warp n-offset
    const int g = lane >> 2, tig = lane & 3;

    // ldmatrix base addresses (byte, shared space) — mapping validated in R9
    Frag F;
    {
        uint32_t sAh = (uint32_t)__cvta_generic_to_shared(Ah);
        uint32_t sAl = (uint32_t)__cvta_generic_to_shared(Al);
        uint32_t sBh = (uint32_t)__cvta_generic_to_shared(Bh);
        uint32_t sBl = (uint32_t)__cvta_generic_to_shared(Bl);
        int arow = (lane & 15), akoff = (lane >> 4) * 8;
        F.aH0 = sAh + ((m0 + arow) * KP + akoff) * 2;
        F.aH1 = sAh + ((m0 + 16 + arow) * KP + akoff) * 2;
        F.aL0 = sAl + ((m0 + arow) * KP + akoff) * 2;
        F.aL1 = sAl + ((m0 + 16 + arow) * KP + akoff) * 2;
        int brow = (lane & 7) + ((lane >> 4) & 1) * 8, bkoff = ((lane >> 3) & 1) * 8;
        F.bH0 = sBh + ((n0 + brow) * KP + bkoff) * 2;
        F.bH1 = sBh + ((n0 + 16 + brow) * KP + bkoff) * 2;
        F.bL0 = sBl + ((n0 + brow) * KP + bkoff) * 2;
        F.bL1 = sBl + ((n0 + 16 + brow) * KP + bkoff) * 2;
    }

    float acc[2][4][4];
    mainloop(F, acc);

    // epilogue: rank-3 verts update + bias
    #pragma unroll
    for (int i = 0; i < 2; i++) {
        int r0 = blockIdx.x * BM + m0 + i * 16 + g;
        int r1 = r0 + 8;
        float vx0 = verts[3 * r0], vy0 = verts[3 * r0 + 1], vz0 = verts[3 * r0 + 2];
        float vx1 = verts[3 * r1], vy1 = verts[3 * r1 + 1], vz1 = verts[3 * r1 + 2];
        #pragma unroll
        for (int j = 0; j < 4; j++) {
            int c = n0 + j * 8 + 2 * tig;
            float w0a = epi[c],       w0b = epi[c + 1];
            float w1a = epi[128 + c], w1b = epi[128 + c + 1];
            float w2a = epi[256 + c], w2b = epi[256 + c + 1];
            float ba  = epi[384 + c], bb2 = epi[384 + c + 1];
            float2 o01, o23;
            o01.x = acc[i][j][0] + vx0 * w0a + vy0 * w1a + vz0 * w2a + ba;
            o01.y = acc[i][j][1] + vx0 * w0b + vy0 * w1b + vz0 * w2b + bb2;
            o23.x = acc[i][j][2] + vx1 * w0a + vy1 * w1a + vz1 * w2a + ba;
            o23.y = acc[i][j][3] + vx1 * w0b + vy1 * w1b + vz1 * w2b + bb2;
            *(float2*)(Out + (size_t)r0 * HID + c) = o01;
            *(float2*)(Out + (size_t)r1 * HID + c) = o23;
        }
    }
}

// ---------------- launch ----------------
extern "C" void kernel_launch(void* const* d_in, const int* in_sizes, int n_in,
                              void* d_out, int out_size) {
    const float* x     = (const float*)d_in[0];
    const float* verts = (const float*)d_in[1];
    const int*   edges = (const int*)  d_in[2];
    const float* bw    = (const float*)d_in[3];
    const float* bb    = (const float*)d_in[4];
    const float* w0    = (const float*)d_in[5];
    const float* b0    = (const float*)d_in[6];
    const float* w1    = (const float*)d_in[7];
    const float* b1    = (const float*)d_in[8];
    const float* ow    = (const float*)d_in[9];
    const float* ob    = (const float*)d_in[10];
    float* out = (float*)d_out;

    float *bufA, *bufB, *bufZ;
    __nv_bfloat16 *Bhi, *Blo;
    cudaGetSymbolAddress((void**)&bufA, g_bufA);
    cudaGetSymbolAddress((void**)&bufB, g_bufB);
    cudaGetSymbolAddress((void**)&bufZ, g_bufZ);
    cudaGetSymbolAddress((void**)&Bhi, g_Bhi);
    cudaGetSymbolAddress((void**)&Blo, g_Blo);

    cudaFuncSetAttribute(gemm_mma_kernel, cudaFuncAttributeMaxDynamicSharedMemorySize, GEMM_SMEM);

    convw_kernel<<<6 * 16384 / 256, 256>>>(w0, w1);
    pixel_proj_kernel<<<NPIX / 2, dim3(HID, 2)>>>(x, bw);
    zero_cnt_kernel<<<NV / 1024, 1024>>>();
    fill_adj_kernel<<<NE / 256, 256>>>(edges);

    // layer 1 (A fused-sampled from g_P)
    gemm_mma_kernel<<<NBLK, 256, GEMM_SMEM>>>(nullptr, verts, Bhi, Blo,
                                              w0, b0, bufB, 1, bb);
    gemm_mma_kernel<<<NBLK, 256, GEMM_SMEM>>>(nullptr, verts, Bhi + 3 * 16384, Blo + 3 * 16384,
                                              w1, b1, bufZ, 1, bb);
    gather_kernel<<<NV / 8, 256>>>(bufZ, bufB);

    // layer 2
    gemm_mma_kernel<<<NBLK, 256, GEMM_SMEM>>>(bufB, verts, Bhi + 1 * 16384, Blo + 1 * 16384,
                                              w0 + (size_t)1 * DIN * HID, b0 + HID, bufA, 0, bb);
    gemm_mma_kernel<<<NBLK, 256, GEMM_SMEM>>>(bufB, verts, Bhi + 4 * 16384, Blo + 4 * 16384,
                                              w1 + (size_t)1 * DIN * HID, b1 + HID, bufZ, 0, bb);
    gather_kernel<<<NV / 8, 256>>>(bufZ, bufA);

    // layer 3 (gather fused with final head)
    gemm_mma_kernel<<<NBLK, 256, GEMM_SMEM>>>(bufA, verts, Bhi + 2 * 16384, Blo + 2 * 16384,
                                              w0 + (size_t)2 * DIN * HID, b0 + 2 * HID, bufB, 0, bb);
    gemm_mma_kernel<<<NBLK, 256, GEMM_SMEM>>>(bufA, verts, Bhi + 5 * 16384, Blo + 5 * 16384,
                                              w1 + (size_t)2 * DIN * HID, b1 + 2 * HID, bufZ, 0, bb);
    gather_final_kernel<<<NV / 8, 256>>>(bufZ, bufB, verts, ow, ob, out);
}

// round 14
// speedup vs baseline: 1.1335x; 1.0038x over previous
#include <cuda_runtime.h>
#include <cuda_bf16.h>
#include <math.h>
#include <stdint.h>

#define NV   262144
#define NE   786432
#define CIMG 256
#define HID  128
#define HW   64
#define NPIX (HW*HW)
#define DIN  (HID+3)
#define BM   64
#define KP   136                 // padded K stride (bf16) -> conflict-free ldmatrix
#define NBLK (NV/BM)             // 4096
#define GRID 148
#define DEGCAP 32

// Scratch (allowed: __device__ globals, no allocation)
__device__ float g_P[NPIX * HID];                  // 2 MB, L2-resident
__device__ float g_bufA[(size_t)NV * HID];
__device__ float g_bufB[(size_t)NV * HID];
__device__ float g_bufZ[(size_t)NV * HID];
__device__ __nv_bfloat16 g_Bhi[6 * 16384];         // weights bf16 hi, [n][k] row-major
__device__ __nv_bfloat16 g_Blo[6 * 16384];         // weights bf16 lo
__device__ int g_cnt[NV];
__device__ int g_adj[(size_t)NV * DEGCAP];

// ---------------- helpers ----------------
__device__ __forceinline__ void mma16816(float* c, const uint32_t* a, const uint32_t* b) {
    asm volatile(
        "mma.sync.aligned.m16n8k16.row.col.f32.bf16.bf16.f32 "
        "{%0,%1,%2,%3}, {%4,%5,%6,%7}, {%8,%9}, {%0,%1,%2,%3};"
        : "+f"(c[0]), "+f"(c[1]), "+f"(c[2]), "+f"(c[3])
        : "r"(a[0]), "r"(a[1]), "r"(a[2]), "r"(a[3]), "r"(b[0]), "r"(b[1]));
}
__device__ __forceinline__ void ldmx4(uint32_t* r, uint32_t addr) {
    asm volatile("ldmatrix.sync.aligned.m8n8.x4.shared.b16 {%0,%1,%2,%3}, [%4];"
        : "=r"(r[0]), "=r"(r[1]), "=r"(r[2]), "=r"(r[3]) : "r"(addr));
}
__device__ __forceinline__ void cp_async16(uint32_t dst, const void* src) {
    asm volatile("cp.async.cg.shared.global [%0], [%1], 16;" :: "r"(dst), "l"(src));
}
__device__ __forceinline__ void cp_commit() {
    asm volatile("cp.async.commit_group;" ::: "memory");
}
template <int N>
__device__ __forceinline__ void cp_wait() {
    asm volatile("cp.async.wait_group %0;" :: "n"(N) : "memory");
}
__device__ __forceinline__ uint32_t pack_bf2(__nv_bfloat16 a, __nv_bfloat16 b) {
    return (uint32_t)__bfloat16_as_ushort(a) | ((uint32_t)__bfloat16_as_ushort(b) << 16);
}
__device__ __forceinline__ void split_store(__nv_bfloat16* Ah, __nv_bfloat16* Al,
                                            int off, float4 v) {
    __nv_bfloat16 hx = __float2bfloat16(v.x), hy = __float2bfloat16(v.y);
    __nv_bfloat16 hz = __float2bfloat16(v.z), hw = __float2bfloat16(v.w);
    uint2 hp, lp;
    hp.x = pack_bf2(hx, hy);
    hp.y = pack_bf2(hz, hw);
    lp.x = pack_bf2(__float2bfloat16(v.x - __bfloat162float(hx)),
                    __float2bfloat16(v.y - __bfloat162float(hy)));
    lp.y = pack_bf2(__float2bfloat16(v.z - __bfloat162float(hz)),
                    __float2bfloat16(v.w - __bfloat162float(hw)));
    *(uint2*)&Ah[off] = hp;
    *(uint2*)&Al[off] = lp;
}

// ---------------- kernel 0: weights -> bf16 hi/lo, [n][k] row-major ----------------
__global__ void convw_kernel(const float* __restrict__ w0, const float* __restrict__ w1) {
    int idx = blockIdx.x * 256 + threadIdx.x;
    int m = idx >> 14;
    int e = idx & 16383;
    int n = e & 127;
    int k = e >> 7;
    const float* W = (m < 3) ? (w0 + (size_t)m * DIN * HID) : (w1 + (size_t)(m - 3) * DIN * HID);
    float v = W[(size_t)k * HID + n];
    __nv_bfloat16 hi = __float2bfloat16(v);
    float lo = v - __bfloat162float(hi);
    g_Bhi[(size_t)m * 16384 + n * 128 + k] = hi;
    g_Blo[(size_t)m * 16384 + n * 128 + k] = __float2bfloat16(lo);
}

// ---------------- kernel 1: P[p][j] = sum_c x[c][p] * bw[c][j] ----------------
__global__ void pixel_proj_kernel(const float* __restrict__ x, const float* __restrict__ bw) {
    int j = threadIdx.x;
    int p = blockIdx.x * blockDim.y + threadIdx.y;
    const float* xp = x + p;
    const float* wp = bw + j;
    float acc = 0.f;
    #pragma unroll 8
    for (int c = 0; c < CIMG; c++)
        acc = fmaf(xp[(size_t)c * NPIX], wp[(size_t)c * HID], acc);
    g_P[(size_t)p * HID + j] = acc;
}

// ---------------- adjacency build ----------------
__global__ void zero_cnt_kernel() {
    int v = blockIdx.x * 1024 + threadIdx.x;
    if (v < NV) g_cnt[v] = 0;
}
__global__ void fill_adj_kernel(const int* __restrict__ edges) {
    int e = blockIdx.x * 256 + threadIdx.x;
    if (e >= NE) return;
    int a = edges[2 * e], b = edges[2 * e + 1];
    int sa = atomicAdd(&g_cnt[a], 1);
    if (sa < DEGCAP) g_adj[(size_t)a * DEGCAP + sa] = b;
    int sb = atomicAdd(&g_cnt[b], 1);
    if (sb < DEGCAP) g_adj[(size_t)b * DEGCAP + sb] = a;
}

// ---------------- gather: Y[v] += sum_nbr Z[nbr]  (in-place on Y) ----------------
__global__ void gather_kernel(const float* __restrict__ Z, float* __restrict__ Y) {
    int v    = (blockIdx.x * blockDim.x + threadIdx.x) >> 5;
    int lane = threadIdx.x & 31;
    if (v >= NV) return;
    int cnt = min(g_cnt[v], DEGCAP);
    int u = (lane < cnt) ? g_adj[(size_t)v * DEGCAP + lane] : 0;
    float4 acc = *(const float4*)(Y + (size_t)v * HID + lane * 4);
    int i = 0;
    for (; i + 2 <= cnt; i += 2) {
        int u0 = __shfl_sync(0xffffffffu, u, i);
        int u1 = __shfl_sync(0xffffffffu, u, i + 1);
        float4 z0 = *(const float4*)(Z + (size_t)u0 * HID + lane * 4);
        float4 z1 = *(const float4*)(Z + (size_t)u1 * HID + lane * 4);
        acc.x += z0.x + z1.x; acc.y += z0.y + z1.y;
        acc.z += z0.z + z1.z; acc.w += z0.w + z1.w;
    }
    if (i < cnt) {
        int u0 = __shfl_sync(0xffffffffu, u, i);
        float4 z0 = *(const float4*)(Z + (size_t)u0 * HID + lane * 4);
        acc.x += z0.x; acc.y += z0.y; acc.z += z0.z; acc.w += z0.w;
    }
    *(float4*)(Y + (size_t)v * HID + lane * 4) = acc;
}

// ---------------- gather + final head fused (layer 3) ----------------
__global__ void gather_final_kernel(const float* __restrict__ Z, const float* __restrict__ Ybuf,
                                    const float* __restrict__ verts,
                                    const float* __restrict__ ow, const float* __restrict__ ob,
                                    float* __restrict__ out) {
    __shared__ float sw[DIN * 3];
    for (int i = threadIdx.x; i < DIN * 3; i += blockDim.x) sw[i] = ow[i];
    __syncthreads();

    int v    = (blockIdx.x * blockDim.x + threadIdx.x) >> 5;
    int lane = threadIdx.x & 31;
    if (v >= NV) return;
    int cnt = min(g_cnt[v], DEGCAP);
    int u = (lane < cnt) ? g_adj[(size_t)v * DEGCAP + lane] : 0;
    float4 acc = *(const float4*)(Ybuf + (size_t)v * HID + lane * 4);
    int i = 0;
    for (; i + 2 <= cnt; i += 2) {
        int u0 = __shfl_sync(0xffffffffu, u, i);
        int u1 = __shfl_sync(0xffffffffu, u, i + 1);
        float4 z0 = *(const float4*)(Z + (size_t)u0 * HID + lane * 4);
        float4 z1 = *(const float4*)(Z + (size_t)u1 * HID + lane * 4);
        acc.x += z0.x + z1.x; acc.y += z0.y + z1.y;
        acc.z += z0.z + z1.z; acc.w += z0.w + z1.w;
    }
    if (i < cnt) {
        int u0 = __shfl_sync(0xffffffffu, u, i);
        float4 z0 = *(const float4*)(Z + (size_t)u0 * HID + lane * 4);
        acc.x += z0.x; acc.y += z0.y; acc.z += z0.z; acc.w += z0.w;
    }

    float4 f;
    f.x = fmaxf(acc.x, 0.f); f.y = fmaxf(acc.y, 0.f);
    f.z = fmaxf(acc.z, 0.f); f.w = fmaxf(acc.w, 0.f);
    int j = lane * 4;
    *(float4*)(out + (size_t)3 * NV + (size_t)v * HID + j) = f;

    float a0 = f.x * sw[(j + 0) * 3 + 0] + f.y * sw[(j + 1) * 3 + 0] + f.z * sw[(j + 2) * 3 + 0] + f.w * sw[(j + 3) * 3 + 0];
    float a1 = f.x * sw[(j + 0) * 3 + 1] + f.y * sw[(j + 1) * 3 + 1] + f.z * sw[(j + 2) * 3 + 1] + f.w * sw[(j + 3) * 3 + 1];
    float a2 = f.x * sw[(j + 0) * 3 + 2] + f.y * sw[(j + 1) * 3 + 2] + f.z * sw[(j + 2) * 3 + 2] + f.w * sw[(j + 3) * 3 + 2];
    #pragma unroll
    for (int off = 16; off > 0; off >>= 1) {
        a0 += __shfl_down_sync(0xffffffffu, a0, off);
        a1 += __shfl_down_sync(0xffffffffu, a1, off);
        a2 += __shfl_down_sync(0xffffffffu, a2, off);
    }
    if (lane == 0) {
        float vx = verts[3 * v], vy = verts[3 * v + 1], vz = verts[3 * v + 2];
        a0 += vx * sw[(HID + 0) * 3 + 0] + vy * sw[(HID + 1) * 3 + 0] + vz * sw[(HID + 2) * 3 + 0] + ob[0];
        a1 += vx * sw[(HID + 0) * 3 + 1] + vy * sw[(HID + 1) * 3 + 1] + vz * sw[(HID + 2) * 3 + 1] + ob[1];
        a2 += vx * sw[(HID + 0) * 3 + 2] + vy * sw[(HID + 1) * 3 + 2] + vz * sw[(HID + 2) * 3 + 2] + ob[2];
        out[3 * v + 0] = vx + tanhf(a0);
        out[3 * v + 1] = vy + tanhf(a1);
        out[3 * v + 2] = vz + tanhf(a2);
    }
}

// ---------------- persistent HMMA GEMM (bf16 hi/lo, ldmatrix, cp.async pipeline) ----------------
// sample_mode=0: A-tile = relu(A[V,128]) (cp.async prefetched)
// sample_mode=1: A-tile = relu(bilinear(g_P, verts) + bbias)
// Out = Atile @ W[0:128] + verts @ W[128:131] + bias
#define OFF_B    0
#define OFF_EPI  (128 * KP * 2 * 2)                  // 69632
#define OFF_RAW  (OFF_EPI + 2048)                    // 71680
#define OFF_A    (OFF_RAW + 2 * BM * HID * 4)        // 71680 + 65536 = 137216
#define GEMM_SMEM (OFF_A + BM * KP * 2 * 2)          // 172032

struct Frag { uint32_t aH0, aH1, aL0, aL1, bH0, bH1, bL0, bL1; };

__device__ __forceinline__ void mainloop(const Frag& F, float acc[2][4][4]) {
    #pragma unroll
    for (int i = 0; i < 2; i++)
        #pragma unroll
        for (int j = 0; j < 4; j++)
            #pragma unroll
            for (int q = 0; q < 4; q++) acc[i][j][q] = 0.f;
    #pragma unroll
    for (int kb = 0; kb < 8; kb++) {
        uint32_t aH[2][4], aL[2][4], bH[2][4], bL[2][4];
        int ko = kb * 32;
        ldmx4(aH[0], F.aH0 + ko); ldmx4(aH[1], F.aH1 + ko);
        ldmx4(aL[0], F.aL0 + ko); ldmx4(aL[1], F.aL1 + ko);
        ldmx4(bH[0], F.bH0 + ko); ldmx4(bH[1], F.bH1 + ko);
        ldmx4(bL[0], F.bL0 + ko); ldmx4(bL[1], F.bL1 + ko);
        #pragma unroll
        for (int i = 0; i < 2; i++)
            #pragma unroll
            for (int j = 0; j < 4; j++) {
                const uint32_t* bh = &bH[j >> 1][(j & 1) * 2];
                const uint32_t* bl = &bL[j >> 1][(j & 1) * 2];
                mma16816(acc[i][j], aH[i], bh);
                mma16816(acc[i][j], aH[i], bl);
                mma16816(acc[i][j], aL[i], bh);
            }
    }
}

__global__ void __launch_bounds__(256, 1)
gemm_mma_kernel(const float* __restrict__ A, const float* __restrict__ verts,
                const __nv_bfloat16* __restrict__ Bhi, const __nv_bfloat16* __restrict__ Blo,
                const float* __restrict__ Wm, const float* __restrict__ bias,
                float* __restrict__ Out, int sample_mode, const float* __restrict__ bbias) {
    extern __shared__ char smraw[];
    __nv_bfloat16* Bh = (__nv_bfloat16*)(smraw + OFF_B);       // 128 x KP
    __nv_bfloat16* Bl = Bh + 128 * KP;
    float* epi = (float*)(smraw + OFF_EPI);
    float* raw = (float*)(smraw + OFF_RAW);                    // 2 x (BM x HID)
    __nv_bfloat16* Ah = (__nv_bfloat16*)(smraw + OFF_A);       // BM x KP
    __nv_bfloat16* Al = Ah + BM * KP;

    const int tid = threadIdx.x, lane = tid & 31, wid = tid >> 5;

    // stage B hi/lo once
    {
        const uint4* gh = (const uint4*)Bhi;
        const uint4* gl = (const uint4*)Blo;
        #pragma unroll
        for (int i = tid; i < 2048; i += 256) {
            int n = i >> 4, kc = (i & 15) * 8;
            *(uint4*)&Bh[n * KP + kc] = gh[i];
            *(uint4*)&Bl[n * KP + kc] = gl[i];
        }
    }
    if (tid < 128) {
        epi[tid]       = Wm[(size_t)(HID + 0) * HID + tid];
        epi[128 + tid] = Wm[(size_t)(HID + 1) * HID + tid];
        epi[256 + tid] = Wm[(size_t)(HID + 2) * HID + tid];
        epi[384 + tid] = bias[tid];
    }

    const int m0 = (wid & 1) * 32;
    const int n0 = (wid >> 1) * 32;
    const int g = lane >> 2, tig = lane & 3;

    Frag F;
    {
        uint32_t sAh = (uint32_t)__cvta_generic_to_shared(Ah);
        uint32_t sAl = (uint32_t)__cvta_generic_to_shared(Al);
        uint32_t sBh = (uint32_t)__cvta_generic_to_shared(Bh);
        uint32_t sBl = (uint32_t)__cvta_generic_to_shared(Bl);
        int arow = (lane & 15), akoff = (lane >> 4) * 8;
        F.aH0 = sAh + ((m0 + arow) * KP + akoff) * 2;
        F.aH1 = sAh + ((m0 + 16 + arow) * KP + akoff) * 2;
        F.aL0 = sAl + ((m0 + arow) * KP + akoff) * 2;
        F.aL1 = sAl + ((m0 + 16 + arow) * KP + akoff) * 2;
        int brow = (lane & 7) + ((lane >> 4) & 1) * 8, bkoff = ((lane >> 3) & 1) * 8;
        F.bH0 = sBh + ((n0 + brow) * KP + bkoff) * 2;
        F.bH1 = sBh + ((n0 + 16 + brow) * KP + bkoff) * 2;
        F.bL0 = sBl + ((n0 + brow) * KP + bkoff) * 2;
        F.bL1 = sBl + ((n0 + 16 + brow) * KP + bkoff) * 2;
    }

    const uint32_t sraw = (uint32_t)__cvta_generic_to_shared(raw);

    if (sample_mode == 0) {
        // prefetch first tile into raw[0]: full 64x128 fp32 tile = 2048 float4
        {
            const float4* src = (const float4*)(A + (size_t)blockIdx.x * BM * HID);
            #pragma unroll
            for (int i = tid; i < 2048; i += 256)
                cp_async16(sraw + i * 16, src + i);
            cp_commit();
        }
        int it = 0;
        for (int t = blockIdx.x; t < NBLK; t += GRID, it++) {
            int cur = it & 1;
            int tn = t + GRID;
            if (tn < NBLK) {
                const float4* src = (const float4*)(A + (size_t)tn * BM * HID);
                #pragma unroll
                for (int i = tid; i < 2048; i += 256)
                    cp_async16(sraw + ((cur ^ 1) * 2048 + i) * 16, src + i);
                cp_commit();
                cp_wait<1>();
            } else {
                cp_wait<0>();
            }
            __syncthreads();
            // convert raw[cur] -> Ah/Al
            const float* rb = raw + cur * BM * HID;
            #pragma unroll
            for (int i = tid; i < BM * HID / 4; i += 256) {
                int r = i >> 5, c = (i & 31) * 4;
                float4 v = *(const float4*)(rb + r * HID + c);
                v.x = fmaxf(v.x, 0.f); v.y = fmaxf(v.y, 0.f);
                v.z = fmaxf(v.z, 0.f); v.w = fmaxf(v.w, 0.f);
                split_store(Ah, Al, r * KP + c, v);
            }
            __syncthreads();

            float acc[2][4][4];
            mainloop(F, acc);

            #pragma unroll
            for (int i = 0; i < 2; i++) {
                int r0 = t * BM + m0 + i * 16 + g;
                int r1 = r0 + 8;
                float vx0 = verts[3 * r0], vy0 = verts[3 * r0 + 1], vz0 = verts[3 * r0 + 2];
                float vx1 = verts[3 * r1], vy1 = verts[3 * r1 + 1], vz1 = verts[3 * r1 + 2];
                #pragma unroll
                for (int j = 0; j < 4; j++) {
                    int c = n0 + j * 8 + 2 * tig;
                    float w0a = epi[c],       w0b = epi[c + 1];
                    float w1a = epi[128 + c], w1b = epi[128 + c + 1];
                    float w2a = epi[256 + c], w2b = epi[256 + c + 1];
                    float ba  = epi[384 + c], bb2 = epi[384 + c + 1];
                    float2 o01, o23;
                    o01.x = acc[i][j][0] + vx0 * w0a + vy0 * w1a + vz0 * w2a + ba;
                    o01.y = acc[i][j][1] + vx0 * w0b + vy0 * w1b + vz0 * w2b + bb2;
                    o23.x = acc[i][j][2] + vx1 * w0a + vy1 * w1a + vz1 * w2a + ba;
                    o23.y = acc[i][j][3] + vx1 * w0b + vy1 * w1b + vz1 * w2b + bb2;
                    *(float2*)(Out + (size_t)r0 * HID + c) = o01;
                    *(float2*)(Out + (size_t)r1 * HID + c) = o23;
                }
            }
            __syncthreads();   // all warps done reading Ah/Al before next convert
        }
    } else {
        // sampled-A persistent loop (g_P is L2-resident; no prefetch needed)
        for (int t = blockIdx.x; t < NBLK; t += GRID) {
            #pragma unroll
            for (int i = tid; i < BM * HID / 4; i += 256) {
                int r = i >> 5, c = (i & 31) * 4;
                int vtx = t * BM + r;
                float vx = verts[3 * vtx], vy = verts[3 * vtx + 1];
                float px = (vx + 1.f) * 0.5f * (HW - 1);
                float py = (vy + 1.f) * 0.5f * (HW - 1);
                float fx = floorf(px), fy = floorf(py);
                float wx = px - fx,    wy = py - fy;
                int x0 = (int)fx; x0 = min(max(x0, 0), HW - 1); int x1 = min(x0 + 1, HW - 1);
                int y0 = (int)fy; y0 = min(max(y0, 0), HW - 1); int y1 = min(y0 + 1, HW - 1);
                const float* P00 = g_P + (size_t)(y0 * HW + x0) * HID;
                const float* P01 = g_P + (size_t)(y0 * HW + x1) * HID;
                const float* P10 = g_P + (size_t)(y1 * HW + x0) * HID;
                const float* P11 = g_P + (size_t)(y1 * HW + x1) * HID;
                float4 a = *(const float4*)(P00 + c);
                float4 b = *(const float4*)(P01 + c);
                float4 cc = *(const float4*)(P10 + c);
                float4 d = *(const float4*)(P11 + c);
                float4 b4 = *(const float4*)(bbias + c);
                float4 v;
                v.x = (a.x * (1.f - wx) + b.x * wx) * (1.f - wy) + (cc.x * (1.f - wx) + d.x * wx) * wy + b4.x;
                v.y = (a.y * (1.f - wx) + b.y * wx) * (1.f - wy) + (cc.y * (1.f - wx) + d.y * wx) * wy + b4.y;
                v.z = (a.z * (1.f - wx) + b.z * wx) * (1.f - wy) + (cc.z * (1.f - wx) + d.z * wx) * wy + b4.z;
                v.w = (a.w * (1.f - wx) + b.w * wx) * (1.f - wy) + (cc.w * (1.f - wx) + d.w * wx) * wy + b4.w;
                v.x = fmaxf(v.x, 0.f); v.y = fmaxf(v.y, 0.f);
                v.z = fmaxf(v.z, 0.f); v.w = fmaxf(v.w, 0.f);
                split_store(Ah, Al, r * KP + c, v);
            }
            __syncthreads();

            float acc[2][4][4];
            mainloop(F, acc);

            #pragma unroll
            for (int i = 0; i < 2; i++) {
                int r0 = t * BM + m0 + i * 16 + g;
                int r1 = r0 + 8;
                float vx0 = verts[3 * r0], vy0 = verts[3 * r0 + 1], vz0 = verts[3 * r0 + 2];
                float vx1 = verts[3 * r1], vy1 = verts[3 * r1 + 1], vz1 = verts[3 * r1 + 2];
                #pragma unroll
                for (int j = 0; j < 4; j++) {
                    int c = n0 + j * 8 + 2 * tig;
                    float w0a = epi[c],       w0b = epi[c + 1];
                    float w1a = epi[128 + c], w1b = epi[128 + c + 1];
                    float w2a = epi[256 + c], w2b = epi[256 + c + 1];
                    float ba  = epi[384 + c], bb2 = epi[384 + c + 1];
                    float2 o01, o23;
                    o01.x = acc[i][j][0] + vx0 * w0a + vy0 * w1a + vz0 * w2a + ba;
                    o01.y = acc[i][j][1] + vx0 * w0b + vy0 * w1b + vz0 * w2b + bb2;
                    o23.x = acc[i][j][2] + vx1 * w0a + vy1 * w1a + vz1 * w2a + ba;
                    o23.y = acc[i][j][3] + vx1 * w0b + vy1 * w1b + vz1 * w2b + bb2;
                    *(float2*)(Out + (size_t)r0 * HID + c) = o01;
                    *(float2*)(Out + (size_t)r1 * HID + c) = o23;
                }
            }
            __syncthreads();
        }
    }
}

// ---------------- launch ----------------
extern "C" void kernel_launch(void* const* d_in, const int* in_sizes, int n_in,
                              void* d_out, int out_size) {
    const float* x     = (const float*)d_in[0];
    const float* verts = (const float*)d_in[1];
    const int*   edges = (const int*)  d_in[2];
    const float* bw    = (const float*)d_in[3];
    const float* bb    = (const float*)d_in[4];
    const float* w0    = (const float*)d_in[5];
    const float* b0    = (const float*)d_in[6];
    const float* w1    = (const float*)d_in[7];
    const float* b1    = (const float*)d_in[8];
    const float* ow    = (const float*)d_in[9];
    const float* ob    = (const float*)d_in[10];
    float* out = (float*)d_out;

    float *bufA, *bufB, *bufZ;
    __nv_bfloat16 *Bhi, *Blo;
    cudaGetSymbolAddress((void**)&bufA, g_bufA);
    cudaGetSymbolAddress((void**)&bufB, g_bufB);
    cudaGetSymbolAddress((void**)&bufZ, g_bufZ);
    cudaGetSymbolAddress((void**)&Bhi, g_Bhi);
    cudaGetSymbolAddress((void**)&Blo, g_Blo);

    cudaFuncSetAttribute(gemm_mma_kernel, cudaFuncAttributeMaxDynamicSharedMemorySize, GEMM_SMEM);

    convw_kernel<<<6 * 16384 / 256, 256>>>(w0, w1);
    pixel_proj_kernel<<<NPIX / 2, dim3(HID, 2)>>>(x, bw);
    zero_cnt_kernel<<<NV / 1024, 1024>>>();
    fill_adj_kernel<<<NE / 256, 256>>>(edges);

    // layer 1 (A fused-sampled from g_P)
    gemm_mma_kernel<<<GRID, 256, GEMM_SMEM>>>(nullptr, verts, Bhi, Blo,
                                              w0, b0, bufB, 1, bb);
    gemm_mma_kernel<<<GRID, 256, GEMM_SMEM>>>(nullptr, verts, Bhi + 3 * 16384, Blo + 3 * 16384,
                                              w1, b1, bufZ, 1, bb);
    gather_kernel<<<NV / 8, 256>>>(bufZ, bufB);

    // layer 2
    gemm_mma_kernel<<<GRID, 256, GEMM_SMEM>>>(bufB, verts, Bhi + 1 * 16384, Blo + 1 * 16384,
                                              w0 + (size_t)1 * DIN * HID, b0 + HID, bufA, 0, bb);
    gemm_mma_kernel<<<GRID, 256, GEMM_SMEM>>>(bufB, verts, Bhi + 4 * 16384, Blo + 4 * 16384,
                                              w1 + (size_t)1 * DIN * HID, b1 + HID, bufZ, 0, bb);
    gather_kernel<<<NV / 8, 256>>>(bufZ, bufA);

    // layer 3 (gather fused with final head)
    gemm_mma_kernel<<<GRID, 256, GEMM_SMEM>>>(bufA, verts, Bhi + 2 * 16384, Blo + 2 * 16384,
                                              w0 + (size_t)2 * DIN * HID, b0 + 2 * HID, bufB, 0, bb);
    gemm_mma_kernel<<<GRID, 256, GEMM_SMEM>>>(bufA, verts, Bhi + 5 * 16384, Blo + 5 * 16384,
                                              w1 + (size_t)2 * DIN * HID, b1 + 2 * HID, bufZ, 0, bb);
    gather_final_kernel<<<NV / 8, 256>>>(bufZ, bufB, verts, ow, ob, out);
}